// round 8
// baseline (speedup 1.0000x reference)
#include <cuda_runtime.h>
#include <cuda_fp16.h>
#include <math.h>
#include <stdint.h>

// Model dims
#define NB   2
#define NT   2048
#define ND   768
#define NH   12
#define NHS  64
#define NL   6
#define NV   50257
#define NTOK (NB*NT)        // 4096
#define NQKV (3*ND)         // 2304
#define NFF  (4*ND)         // 3072

#define TCR  128            // tensor-half rows per CTA
#define FMR  96             // fma-half rows per CTA
#define TILEM (TCR+FMR)     // 224 rows per CTA

// ---------------- scratch (static device memory; no allocations) -----------
__device__ float g_x[NTOK*ND];
__device__ float g_h[NTOK*ND];
__device__ float g_qkv[(size_t)NTOK*NQKV];
__device__ float g_o[NTOK*ND];
__device__ float g_mlp[(size_t)NTOK*NFF];
__device__ float g_wqkvT[(size_t)NL*NQKV*ND];     // [l][n][k]
__device__ float g_woT [(size_t)NL*ND*ND];        // [l][n][k]
__device__ float g_w1T [(size_t)NL*NFF*ND];       // [l][n][k]
__device__ float g_w2T [(size_t)NL*ND*NFF];       // [l][n][k]
__device__ float g_headT[(size_t)NV*ND];          // [n][k]
__device__ float g_loss;

// ---------------- small utility kernels ------------------------------------
__global__ void reset_loss_kernel() { g_loss = 0.0f; }

__global__ void repack_qkv_kernel(const float* __restrict__ wq,
                                  const float* __restrict__ wk,
                                  const float* __restrict__ wv) {
    int i = blockIdx.x * 256 + threadIdx.x;
    const int total = NL * NQKV * ND;
    if (i >= total) return;
    int d = i % ND;
    int c = (i / ND) % NQKV;
    int l = i / (ND * NQKV);
    int sec = c / ND;
    int c2  = c % ND;
    int h   = c2 / NHS;
    int e   = c2 % NHS;
    const float* w = (sec == 0) ? wq : (sec == 1) ? wk : wv;
    g_wqkvT[i] = w[(((size_t)l * NH + h) * ND + d) * NHS + e];
}

__global__ void transpose_kernel(const float* __restrict__ src,
                                 float* __restrict__ dst, int R, int C) {
    __shared__ float t[32][33];
    size_t boff = (size_t)blockIdx.z * R * C;
    int c0 = blockIdx.x * 32, r0 = blockIdx.y * 32;
#pragma unroll
    for (int i = 0; i < 32; i += 8) {
        int x = c0 + threadIdx.x, y = r0 + threadIdx.y + i;
        if (x < C && y < R) t[threadIdx.y + i][threadIdx.x] = src[boff + (size_t)y * C + x];
    }
    __syncthreads();
#pragma unroll
    for (int i = 0; i < 32; i += 8) {
        int x = r0 + threadIdx.x, y = c0 + threadIdx.y + i;
        if (x < R && y < C) dst[boff + (size_t)y * R + x] = t[threadIdx.x][threadIdx.y + i];
    }
}

__global__ void embed_kernel(const int* __restrict__ idx,
                             const float* __restrict__ tok,
                             const float* __restrict__ pos) {
    int i = blockIdx.x * 256 + threadIdx.x;
    if (i >= NTOK * ND) return;
    int d = i % ND;
    int row = i / ND;
    int t = row % NT;
    int tokid = idx[row];
    g_x[i] = tok[(size_t)tokid * ND + d] + pos[t * ND + d];
}

// ---------------- layernorm -------------------------------------------------
__global__ __launch_bounds__(256)
void ln_kernel(const float* __restrict__ x, const float* __restrict__ s,
               const float* __restrict__ b, float* __restrict__ out) {
    __shared__ float red[256];
    int row = blockIdx.x, tid = threadIdx.x;
    const float* xr = x + (size_t)row * ND;
    float v0 = xr[tid], v1 = xr[tid + 256], v2 = xr[tid + 512];
    red[tid] = v0 + v1 + v2;
    __syncthreads();
    for (int off = 128; off; off >>= 1) {
        if (tid < off) red[tid] += red[tid + off];
        __syncthreads();
    }
    float mean = red[0] * (1.0f / ND);
    __syncthreads();
    float d0 = v0 - mean, d1 = v1 - mean, d2 = v2 - mean;
    red[tid] = d0 * d0 + d1 * d1 + d2 * d2;
    __syncthreads();
    for (int off = 128; off; off >>= 1) {
        if (tid < off) red[tid] += red[tid + off];
        __syncthreads();
    }
    float rstd = rsqrtf(red[0] * (1.0f / ND) + 1e-5f);
    float* orow = out + (size_t)row * ND;
    orow[tid]       = d0 * rstd * s[tid]       + b[tid];
    orow[tid + 256] = d1 * rstd * s[tid + 256] + b[tid + 256];
    orow[tid + 512] = d2 * rstd * s[tid + 512] + b[tid + 512];
}

// ---------------- dual-pipe warp-specialized GEMM ---------------------------
// C[MxN] = A[MxK] @ Bt[NxK]^T  (+bias, +relu, +resid)
// One CTA covers a 224x128 tile of C:
//   warps 0-3 (threads 0-127):   rows [row0, row0+128)  via fp16 mma.sync
//   warps 4-7 (threads 128-255): rows [row0+128, row0+224) via fp32 FFMA
// One warp of each type per SMSP -> tensor and FMA pipes run concurrently.
// Independent smem regions and named barriers (1 = tensor, 2 = fma).
// K multiple of 16; M, N ragged safe (clamped loads, guarded stores).

#define HSTR 24   // halves per smem row (tensor half)

template <int EPI>  // bit0: +bias[n], bit1: relu, bit2: +resid[m,n]
__global__ __launch_bounds__(256, 1)
void dp_gemm(const float* __restrict__ A, const float* __restrict__ Bt,
             const float* __restrict__ bias, const float* __restrict__ resid,
             float* __restrict__ C, int M, int N, int K) {
    __shared__ __align__(16) __half Ah[128 * HSTR];   // 6 KB
    __shared__ __align__(16) __half Bh[128 * HSTR];   // 6 KB
    __shared__ __align__(16) float  Af[8][FMR];       // 3 KB
    __shared__ __align__(16) float  Bf[8][128];       // 4 KB

    const int tid  = threadIdx.x;
    const int row0 = blockIdx.x * TILEM, col0 = blockIdx.y * 128;

    if (tid < 128) {
        // ===================== tensor half (fp16 mma) =====================
        const int lane = tid & 31;
        const int warp = tid >> 5;              // 0..3
        const int wm = (warp >> 1) * 64;
        const int wn = (warp & 1) * 64;

        float acc[4][8][4];
#pragma unroll
        for (int mf = 0; mf < 4; mf++)
#pragma unroll
            for (int nf = 0; nf < 8; nf++)
#pragma unroll
                for (int j = 0; j < 4; j++) acc[mf][nf][j] = 0.0f;

        const int arow = (row0 + tid < M) ? (row0 + tid) : (M - 1);
        const float* Ap = A + (size_t)arow * K;
        const int  brow = col0 + tid;
        const bool bok  = brow < N;
        const float* Bp = Bt + (size_t)(bok ? brow : 0) * K;

        float4 pa[4], pb[4];
        const int KT = K / 16;

        // initial load
#pragma unroll
        for (int i = 0; i < 4; i++) {
            pa[i] = *reinterpret_cast<const float4*>(Ap + i * 4);
            pb[i] = bok ? *reinterpret_cast<const float4*>(Bp + i * 4)
                        : make_float4(0.f, 0.f, 0.f, 0.f);
        }

        for (int kt = 0; kt < KT; kt++) {
            // store tile to smem (fp16)
#pragma unroll
            for (int i = 0; i < 4; i++) {
                *reinterpret_cast<__half2*>(&Ah[tid * HSTR + i * 4])     = __floats2half2_rn(pa[i].x, pa[i].y);
                *reinterpret_cast<__half2*>(&Ah[tid * HSTR + i * 4 + 2]) = __floats2half2_rn(pa[i].z, pa[i].w);
                *reinterpret_cast<__half2*>(&Bh[tid * HSTR + i * 4])     = __floats2half2_rn(pb[i].x, pb[i].y);
                *reinterpret_cast<__half2*>(&Bh[tid * HSTR + i * 4 + 2]) = __floats2half2_rn(pb[i].z, pb[i].w);
            }
            asm volatile("bar.sync 1, 128;" ::: "memory");

            if (kt + 1 < KT) {
                int k0 = (kt + 1) * 16;
#pragma unroll
                for (int i = 0; i < 4; i++) {
                    pa[i] = *reinterpret_cast<const float4*>(Ap + k0 + i * 4);
                    pb[i] = bok ? *reinterpret_cast<const float4*>(Bp + k0 + i * 4)
                                : make_float4(0.f, 0.f, 0.f, 0.f);
                }
            }

            const int g   = lane >> 2;
            const int kq2 = (lane & 3) * 2;
            unsigned af[4][4], bf[8][2];
#pragma unroll
            for (int mf = 0; mf < 4; mf++) {
                int m = wm + mf * 16 + g;
                af[mf][0] = *reinterpret_cast<const unsigned*>(&Ah[m * HSTR + kq2]);
                af[mf][1] = *reinterpret_cast<const unsigned*>(&Ah[(m + 8) * HSTR + kq2]);
                af[mf][2] = *reinterpret_cast<const unsigned*>(&Ah[m * HSTR + kq2 + 8]);
                af[mf][3] = *reinterpret_cast<const unsigned*>(&Ah[(m + 8) * HSTR + kq2 + 8]);
            }
#pragma unroll
            for (int nf = 0; nf < 8; nf++) {
                int n = wn + nf * 8 + g;
                bf[nf][0] = *reinterpret_cast<const unsigned*>(&Bh[n * HSTR + kq2]);
                bf[nf][1] = *reinterpret_cast<const unsigned*>(&Bh[n * HSTR + kq2 + 8]);
            }
#pragma unroll
            for (int mf = 0; mf < 4; mf++)
#pragma unroll
                for (int nf = 0; nf < 8; nf++)
                    asm volatile(
                        "mma.sync.aligned.m16n8k16.row.col.f32.f16.f16.f32 "
                        "{%0,%1,%2,%3}, {%4,%5,%6,%7}, {%8,%9}, {%0,%1,%2,%3};"
                        : "+f"(acc[mf][nf][0]), "+f"(acc[mf][nf][1]),
                          "+f"(acc[mf][nf][2]), "+f"(acc[mf][nf][3])
                        : "r"(af[mf][0]), "r"(af[mf][1]), "r"(af[mf][2]), "r"(af[mf][3]),
                          "r"(bf[nf][0]), "r"(bf[nf][1]));
            asm volatile("bar.sync 1, 128;" ::: "memory");
        }

        // epilogue
#pragma unroll
        for (int mf = 0; mf < 4; mf++) {
            int r0 = row0 + wm + mf * 16 + (lane >> 2);
#pragma unroll
            for (int nf = 0; nf < 8; nf++) {
                int n0 = col0 + wn + nf * 8 + 2 * (lane & 3);
#pragma unroll
                for (int half = 0; half < 2; half++) {
                    int r = r0 + half * 8;
#pragma unroll
                    for (int j = 0; j < 2; j++) {
                        int n = n0 + j;
                        if (r < M && n < N) {
                            float v = acc[mf][nf][half * 2 + j];
                            if (EPI & 1) v += bias[n];
                            if (EPI & 2) v = fmaxf(v, 0.0f);
                            if (EPI & 4) v += resid[(size_t)r * N + n];
                            C[(size_t)r * N + n] = v;
                        }
                    }
                }
            }
        }
    } else {
        // ===================== fma half (fp32 FFMA) =====================
        const int wg = tid - 128;          // 0..127
        const int tx = wg & 15;            // 16 cols of threads
        const int ty = wg >> 4;            // 8 rows of threads
        const int rowF0 = row0 + TCR;

        float acc[12][8];
#pragma unroll
        for (int i = 0; i < 12; i++)
#pragma unroll
            for (int j = 0; j < 8; j++) acc[i][j] = 0.0f;

        // A loader: threads wg<96 each own one of the 96 rows
        const int  ar   = (wg < 96) ? wg : 0;
        const int  arow = (rowF0 + ar < M) ? (rowF0 + ar) : (M - 1);
        const float* Ap = A + (size_t)arow * K;
        // B loader: every thread owns one of the 128 B rows
        const int  bn  = wg;
        const bool bok = (col0 + bn) < N;
        const float* Bp = Bt + (size_t)(bok ? (col0 + bn) : 0) * K;

        const int CH = K / 8;
        for (int c = 0; c < CH; c++) {
            const int k0 = c * 8;
            float4 va0, va1, vb0, vb1;
            va0 = *reinterpret_cast<const float4*>(Ap + k0);
            va1 = *reinterpret_cast<const float4*>(Ap + k0 + 4);
            vb0 = bok ? *reinterpret_cast<const float4*>(Bp + k0)
                      : make_float4(0.f, 0.f, 0.f, 0.f);
            vb1 = bok ? *reinterpret_cast<const float4*>(Bp + k0 + 4)
                      : make_float4(0.f, 0.f, 0.f, 0.f);

            asm volatile("bar.sync 2, 128;" ::: "memory");  // prev compute done
            if (wg < 96) {
                Af[0][ar] = va0.x; Af[1][ar] = va0.y; Af[2][ar] = va0.z; Af[3][ar] = va0.w;
                Af[4][ar] = va1.x; Af[5][ar] = va1.y; Af[6][ar] = va1.z; Af[7][ar] = va1.w;
            }
            Bf[0][bn] = vb0.x; Bf[1][bn] = vb0.y; Bf[2][bn] = vb0.z; Bf[3][bn] = vb0.w;
            Bf[4][bn] = vb1.x; Bf[5][bn] = vb1.y; Bf[6][bn] = vb1.z; Bf[7][bn] = vb1.w;
            asm volatile("bar.sync 2, 128;" ::: "memory");  // tile visible

#pragma unroll
            for (int kk = 0; kk < 8; kk++) {
                float4 a0 = *reinterpret_cast<const float4*>(&Af[kk][ty * 12]);
                float4 a1 = *reinterpret_cast<const float4*>(&Af[kk][ty * 12 + 4]);
                float4 a2 = *reinterpret_cast<const float4*>(&Af[kk][ty * 12 + 8]);
                float4 b0 = *reinterpret_cast<const float4*>(&Bf[kk][tx * 8]);
                float4 b1 = *reinterpret_cast<const float4*>(&Bf[kk][tx * 8 + 4]);
                float av[12] = {a0.x, a0.y, a0.z, a0.w, a1.x, a1.y, a1.z, a1.w,
                                a2.x, a2.y, a2.z, a2.w};
                float bv[8]  = {b0.x, b0.y, b0.z, b0.w, b1.x, b1.y, b1.z, b1.w};
#pragma unroll
                for (int i = 0; i < 12; i++)
#pragma unroll
                    for (int j = 0; j < 8; j++)
                        acc[i][j] = fmaf(av[i], bv[j], acc[i][j]);
            }
        }

        // epilogue
#pragma unroll
        for (int i = 0; i < 12; i++) {
            int r = rowF0 + ty * 12 + i;
#pragma unroll
            for (int j = 0; j < 8; j++) {
                int n = col0 + tx * 8 + j;
                if (r < M && n < N) {
                    float v = acc[i][j];
                    if (EPI & 1) v += bias[n];
                    if (EPI & 2) v = fmaxf(v, 0.0f);
                    if (EPI & 4) v += resid[(size_t)r * N + n];
                    C[(size_t)r * N + n] = v;
                }
            }
        }
    }
}

// ---------------- streaming causal attention (warp = 4 queries) ------------
__global__ __launch_bounds__(256)
void attn_kernel(const float* __restrict__ qkv, float* __restrict__ o) {
    int wid = blockIdx.x * 8 + (threadIdx.x >> 5);
    int lane = threadIdx.x & 31;
    const int warps_per_head = NT / 4;  // 512
    int bh = wid / warps_per_head;
    int t0 = (wid % warps_per_head) * 4;
    int b = bh / NH, h = bh % NH;

    const float* base = qkv + (size_t)b * NT * NQKV;
    const float* qb = base + h * NHS;
    const float* kb = base + ND + h * NHS;
    const float* vb = base + 2 * ND + h * NHS;

    float q0[4], q1[4];
#pragma unroll
    for (int i = 0; i < 4; i++) {
        q0[i] = qb[(size_t)(t0 + i) * NQKV + lane];
        q1[i] = qb[(size_t)(t0 + i) * NQKV + 32 + lane];
    }
    float m[4], l[4], a0[4], a1[4];
#pragma unroll
    for (int i = 0; i < 4; i++) { m[i] = -1e30f; l[i] = 0.f; a0[i] = 0.f; a1[i] = 0.f; }

    const float scale = 0.125f;
    int send = t0 + 3;
    for (int s = 0; s <= send; s++) {
        size_t off = (size_t)s * NQKV + lane;
        float k0v = kb[off], k1v = kb[off + 32];
        float v0v = vb[off], v1v = vb[off + 32];
#pragma unroll
        for (int i = 0; i < 4; i++) {
            float p = q0[i] * k0v + q1[i] * k1v;
            p += __shfl_xor_sync(0xffffffffu, p, 16);
            p += __shfl_xor_sync(0xffffffffu, p, 8);
            p += __shfl_xor_sync(0xffffffffu, p, 4);
            p += __shfl_xor_sync(0xffffffffu, p, 2);
            p += __shfl_xor_sync(0xffffffffu, p, 1);
            if (s <= t0 + i) {
                float sc = p * scale;
                float mn = fmaxf(m[i], sc);
                float corr = __expf(m[i] - mn);
                float e = __expf(sc - mn);
                l[i]  = l[i]  * corr + e;
                a0[i] = a0[i] * corr + e * v0v;
                a1[i] = a1[i] * corr + e * v1v;
                m[i] = mn;
            }
        }
    }
#pragma unroll
    for (int i = 0; i < 4; i++) {
        size_t oo = (size_t)(b * NT + t0 + i) * ND + h * NHS + lane;
        o[oo]      = a0[i] / l[i];
        o[oo + 32] = a1[i] / l[i];
    }
}

// ---------------- loss ------------------------------------------------------
__global__ __launch_bounds__(256)
void loss_kernel(const float* __restrict__ logits, const int* __restrict__ targets) {
    __shared__ float sm_[256], sl_[256];
    int row = blockIdx.x, tid = threadIdx.x;
    const float* lr = logits + (size_t)row * NV;
    float m = -1e30f, l = 0.0f;
    for (int j = tid; j < NV; j += 256) {
        float v = lr[j];
        float mn = fmaxf(m, v);
        l = l * __expf(m - mn) + __expf(v - mn);
        m = mn;
    }
    sm_[tid] = m; sl_[tid] = l;
    __syncthreads();
    for (int off = 128; off; off >>= 1) {
        if (tid < off) {
            float m2 = sm_[tid + off], l2 = sl_[tid + off];
            float mn = fmaxf(sm_[tid], m2);
            sl_[tid] = sl_[tid] * __expf(sm_[tid] - mn) + l2 * __expf(m2 - mn);
            sm_[tid] = mn;
        }
        __syncthreads();
    }
    if (tid == 0) {
        float lp = lr[targets[row]] - sm_[0] - logf(sl_[0]);
        atomicAdd(&g_loss, -lp * (1.0f / NTOK));
    }
}

__global__ void finalize_loss_kernel(float* out, int out_size) {
    long long pos = (long long)NTOK * NV;
    if ((long long)out_size > pos) out[pos] = g_loss;
}

// ---------------- host orchestration ----------------------------------------
extern "C" void kernel_launch(void* const* d_in, const int* in_sizes, int n_in,
                              void* d_out, int out_size) {
    const int*   idx     = (const int*)d_in[0];
    const int*   targets = (const int*)d_in[1];
    const float* tok_emb = (const float*)d_in[2];
    const float* pos_emb = (const float*)d_in[3];
    const float* wq      = (const float*)d_in[4];
    const float* wk      = (const float*)d_in[5];
    const float* wv      = (const float*)d_in[6];
    const float* wo      = (const float*)d_in[7];
    const float* bo      = (const float*)d_in[8];
    const float* ln1_s   = (const float*)d_in[9];
    const float* ln1_b   = (const float*)d_in[10];
    const float* ln2_s   = (const float*)d_in[11];
    const float* ln2_b   = (const float*)d_in[12];
    const float* w1      = (const float*)d_in[13];
    const float* b1      = (const float*)d_in[14];
    const float* w2      = (const float*)d_in[15];
    const float* b2      = (const float*)d_in[16];
    const float* lnf_s   = (const float*)d_in[17];
    const float* lnf_b   = (const float*)d_in[18];
    const float* head_w  = (const float*)d_in[19];
    const float* head_b  = (const float*)d_in[20];
    float* out = (float*)d_out;
    (void)in_sizes; (void)n_in;

    float *px, *ph, *pqkv, *po, *pmlp;
    float *pwqkvT, *pwoT, *pw1T, *pw2T, *pheadT;
    cudaGetSymbolAddress((void**)&px,     g_x);
    cudaGetSymbolAddress((void**)&ph,     g_h);
    cudaGetSymbolAddress((void**)&pqkv,   g_qkv);
    cudaGetSymbolAddress((void**)&po,     g_o);
    cudaGetSymbolAddress((void**)&pmlp,   g_mlp);
    cudaGetSymbolAddress((void**)&pwqkvT, g_wqkvT);
    cudaGetSymbolAddress((void**)&pwoT,   g_woT);
    cudaGetSymbolAddress((void**)&pw1T,   g_w1T);
    cudaGetSymbolAddress((void**)&pw2T,   g_w2T);
    cudaGetSymbolAddress((void**)&pheadT, g_headT);

    reset_loss_kernel<<<1, 1>>>();
    {
        int total = NL * NQKV * ND;
        repack_qkv_kernel<<<(total + 255) / 256, 256>>>(wq, wk, wv);
    }
    {
        dim3 blk(32, 8);
        transpose_kernel<<<dim3(24, 24, NL), blk>>>(wo, pwoT, ND, ND);
        transpose_kernel<<<dim3(96, 24, NL), blk>>>(w1, pw1T, ND, NFF);
        transpose_kernel<<<dim3(24, 96, NL), blk>>>(w2, pw2T, NFF, ND);
        transpose_kernel<<<dim3((NV + 31) / 32, 24, 1), blk>>>(head_w, pheadT, ND, NV);
    }
    {
        int total = NTOK * ND;
        embed_kernel<<<(total + 255) / 256, 256>>>(idx, tok_emb, pos_emb);
    }

    const int GM = (NTOK + TILEM - 1) / TILEM;   // 19 M-panels of 224
    dim3 gQKV(GM, NQKV / 128);
    dim3 gD(GM, ND / 128);
    dim3 gFF(GM, NFF / 128);
    dim3 gV(GM, (NV + 127) / 128);

    for (int l = 0; l < NL; l++) {
        ln_kernel<<<NTOK, 256>>>(px, ln1_s + l * ND, ln1_b + l * ND, ph);
        dp_gemm<0><<<gQKV, 256>>>(ph, pwqkvT + (size_t)l * NQKV * ND,
                                  nullptr, nullptr, pqkv, NTOK, NQKV, ND);
        attn_kernel<<<NB * NH * NT / 4 / 8, 256>>>(pqkv, po);
        dp_gemm<5><<<gD, 256>>>(po, pwoT + (size_t)l * ND * ND,
                                bo + l * ND, px, px, NTOK, ND, ND);
        ln_kernel<<<NTOK, 256>>>(px, ln2_s + l * ND, ln2_b + l * ND, ph);
        dp_gemm<3><<<gFF, 256>>>(ph, pw1T + (size_t)l * ND * NFF,
                                 b1 + l * NFF, nullptr, pmlp, NTOK, NFF, ND);
        dp_gemm<5><<<gD, 256>>>(pmlp, pw2T + (size_t)l * NFF * ND,
                                b2 + l * ND, px, px, NTOK, ND, NFF);
    }

    ln_kernel<<<NTOK, 256>>>(px, lnf_s, lnf_b, ph);
    dp_gemm<1><<<gV, 256>>>(ph, pheadT, head_b, nullptr, out, NTOK, NV, ND);
    loss_kernel<<<NTOK, 256>>>(out, targets);
    finalize_loss_kernel<<<1, 1>>>(out, out_size);
}

// round 9
// speedup vs baseline: 1.3891x; 1.3891x over previous
#include <cuda_runtime.h>
#include <cuda_fp16.h>
#include <math.h>
#include <stdint.h>

// Model dims
#define NB   2
#define NT   2048
#define ND   768
#define NH   12
#define NHS  64
#define NL   6
#define NV   50257
#define NTOK (NB*NT)        // 4096
#define NQKV (3*ND)         // 2304
#define NFF  (4*ND)         // 3072

// ---------------- scratch (static device memory; no allocations) -----------
__device__ float g_x[NTOK*ND];
__device__ float g_h[NTOK*ND];
__device__ float g_qkv[(size_t)NTOK*NQKV];
__device__ float g_o[NTOK*ND];
__device__ float g_mlp[(size_t)NTOK*NFF];
__device__ float g_wqkvT[(size_t)NL*NQKV*ND];     // [l][n][k]
__device__ float g_woT [(size_t)NL*ND*ND];        // [l][n][k]
__device__ float g_w1T [(size_t)NL*NFF*ND];       // [l][n][k]
__device__ float g_w2T [(size_t)NL*ND*NFF];       // [l][n][k]
__device__ float g_headT[(size_t)NV*ND];          // [n][k]
__device__ float g_loss;

// ---------------- small utility kernels ------------------------------------
__global__ void reset_loss_kernel() { g_loss = 0.0f; }

__global__ void repack_qkv_kernel(const float* __restrict__ wq,
                                  const float* __restrict__ wk,
                                  const float* __restrict__ wv) {
    int i = blockIdx.x * 256 + threadIdx.x;
    const int total = NL * NQKV * ND;
    if (i >= total) return;
    int d = i % ND;
    int c = (i / ND) % NQKV;
    int l = i / (ND * NQKV);
    int sec = c / ND;
    int c2  = c % ND;
    int h   = c2 / NHS;
    int e   = c2 % NHS;
    const float* w = (sec == 0) ? wq : (sec == 1) ? wk : wv;
    g_wqkvT[i] = w[(((size_t)l * NH + h) * ND + d) * NHS + e];
}

__global__ void transpose_kernel(const float* __restrict__ src,
                                 float* __restrict__ dst, int R, int C) {
    __shared__ float t[32][33];
    size_t boff = (size_t)blockIdx.z * R * C;
    int c0 = blockIdx.x * 32, r0 = blockIdx.y * 32;
#pragma unroll
    for (int i = 0; i < 32; i += 8) {
        int x = c0 + threadIdx.x, y = r0 + threadIdx.y + i;
        if (x < C && y < R) t[threadIdx.y + i][threadIdx.x] = src[boff + (size_t)y * C + x];
    }
    __syncthreads();
#pragma unroll
    for (int i = 0; i < 32; i += 8) {
        int x = r0 + threadIdx.x, y = c0 + threadIdx.y + i;
        if (x < R && y < C) dst[boff + (size_t)y * R + x] = t[threadIdx.x][threadIdx.y + i];
    }
}

__global__ void embed_kernel(const int* __restrict__ idx,
                             const float* __restrict__ tok,
                             const float* __restrict__ pos) {
    int i = blockIdx.x * 256 + threadIdx.x;
    if (i >= NTOK * ND) return;
    int d = i % ND;
    int row = i / ND;
    int t = row % NT;
    int tokid = idx[row];
    g_x[i] = tok[(size_t)tokid * ND + d] + pos[t * ND + d];
}

// ---------------- layernorm -------------------------------------------------
__global__ __launch_bounds__(256)
void ln_kernel(const float* __restrict__ x, const float* __restrict__ s,
               const float* __restrict__ b, float* __restrict__ out) {
    __shared__ float red[256];
    int row = blockIdx.x, tid = threadIdx.x;
    const float* xr = x + (size_t)row * ND;
    float v0 = xr[tid], v1 = xr[tid + 256], v2 = xr[tid + 512];
    red[tid] = v0 + v1 + v2;
    __syncthreads();
    for (int off = 128; off; off >>= 1) {
        if (tid < off) red[tid] += red[tid + off];
        __syncthreads();
    }
    float mean = red[0] * (1.0f / ND);
    __syncthreads();
    float d0 = v0 - mean, d1 = v1 - mean, d2 = v2 - mean;
    red[tid] = d0 * d0 + d1 * d1 + d2 * d2;
    __syncthreads();
    for (int off = 128; off; off >>= 1) {
        if (tid < off) red[tid] += red[tid + off];
        __syncthreads();
    }
    float rstd = rsqrtf(red[0] * (1.0f / ND) + 1e-5f);
    float* orow = out + (size_t)row * ND;
    orow[tid]       = d0 * rstd * s[tid]       + b[tid];
    orow[tid + 256] = d1 * rstd * s[tid + 256] + b[tid + 256];
    orow[tid + 512] = d2 * rstd * s[tid + 512] + b[tid + 512];
}

// ---------------- FP16 tensor-core GEMM (R6 baseline, proven) ---------------
// C[MxN] = A[MxK] @ Bt[NxK]^T  (+bias, +relu, +resid)
// Block 128x128, BK=16, 256 threads = 8 warps (2x4), warp tile 64x32.

#define HSTR 24   // halves per smem row

template <int EPI>  // bit0: +bias[n], bit1: relu, bit2: +resid[m,n]
__global__ __launch_bounds__(256)
void hgemm(const float* __restrict__ A, const float* __restrict__ Bt,
           const float* __restrict__ bias, const float* __restrict__ resid,
           float* __restrict__ C, int M, int N, int K) {
    __shared__ __align__(16) __half As[128 * HSTR];
    __shared__ __align__(16) __half Bs[128 * HSTR];
    const int tid  = threadIdx.x;
    const int lane = tid & 31;
    const int warp = tid >> 5;
    const int wm = (warp >> 2) * 64;
    const int wn = (warp & 3) * 32;
    const int row0 = blockIdx.x * 128, col0 = blockIdx.y * 128;

    float acc[4][4][4];
#pragma unroll
    for (int mf = 0; mf < 4; mf++)
#pragma unroll
        for (int nf = 0; nf < 4; nf++)
#pragma unroll
            for (int j = 0; j < 4; j++) acc[mf][nf][j] = 0.0f;

    float4 pa[2], pb[2];
    const int KT = K / 16;

#define LOADT(k0)                                                             \
    {                                                                         \
        _Pragma("unroll")                                                     \
        for (int i = 0; i < 2; i++) {                                         \
            int idx = tid * 2 + i; int r = idx >> 2, kc = idx & 3;            \
            pa[i] = *reinterpret_cast<const float4*>(                         \
                A + (size_t)(row0 + r) * K + (k0) + kc * 4);                  \
            int rb = col0 + r;                                                \
            if (rb < N)                                                       \
                pb[i] = *reinterpret_cast<const float4*>(                     \
                    Bt + (size_t)rb * K + (k0) + kc * 4);                     \
            else                                                              \
                pb[i] = make_float4(0.f, 0.f, 0.f, 0.f);                      \
        }                                                                     \
    }
#define STST()                                                                \
    {                                                                         \
        _Pragma("unroll")                                                     \
        for (int i = 0; i < 2; i++) {                                         \
            int idx = tid * 2 + i; int r = idx >> 2, kc = idx & 3;            \
            __half2 a0 = __floats2half2_rn(pa[i].x, pa[i].y);                 \
            __half2 a1 = __floats2half2_rn(pa[i].z, pa[i].w);                 \
            __half2 b0 = __floats2half2_rn(pb[i].x, pb[i].y);                 \
            __half2 b1 = __floats2half2_rn(pb[i].z, pb[i].w);                 \
            *reinterpret_cast<__half2*>(&As[r * HSTR + kc * 4])     = a0;     \
            *reinterpret_cast<__half2*>(&As[r * HSTR + kc * 4 + 2]) = a1;     \
            *reinterpret_cast<__half2*>(&Bs[r * HSTR + kc * 4])     = b0;     \
            *reinterpret_cast<__half2*>(&Bs[r * HSTR + kc * 4 + 2]) = b1;     \
        }                                                                     \
    }

    LOADT(0);
    for (int kt = 0; kt < KT; kt++) {
        STST();
        __syncthreads();
        if (kt + 1 < KT) LOADT((kt + 1) * 16);

        const int g   = lane >> 2;
        const int kq2 = (lane & 3) * 2;
        unsigned af[4][4], bf[4][2];
#pragma unroll
        for (int mf = 0; mf < 4; mf++) {
            int m = wm + mf * 16 + g;
            af[mf][0] = *reinterpret_cast<const unsigned*>(&As[m * HSTR + kq2]);
            af[mf][1] = *reinterpret_cast<const unsigned*>(&As[(m + 8) * HSTR + kq2]);
            af[mf][2] = *reinterpret_cast<const unsigned*>(&As[m * HSTR + kq2 + 8]);
            af[mf][3] = *reinterpret_cast<const unsigned*>(&As[(m + 8) * HSTR + kq2 + 8]);
        }
#pragma unroll
        for (int nf = 0; nf < 4; nf++) {
            int n = wn + nf * 8 + g;
            bf[nf][0] = *reinterpret_cast<const unsigned*>(&Bs[n * HSTR + kq2]);
            bf[nf][1] = *reinterpret_cast<const unsigned*>(&Bs[n * HSTR + kq2 + 8]);
        }
#pragma unroll
        for (int mf = 0; mf < 4; mf++)
#pragma unroll
            for (int nf = 0; nf < 4; nf++)
                asm volatile(
                    "mma.sync.aligned.m16n8k16.row.col.f32.f16.f16.f32 "
                    "{%0,%1,%2,%3}, {%4,%5,%6,%7}, {%8,%9}, {%0,%1,%2,%3};"
                    : "+f"(acc[mf][nf][0]), "+f"(acc[mf][nf][1]),
                      "+f"(acc[mf][nf][2]), "+f"(acc[mf][nf][3])
                    : "r"(af[mf][0]), "r"(af[mf][1]), "r"(af[mf][2]), "r"(af[mf][3]),
                      "r"(bf[nf][0]), "r"(bf[nf][1]));
        __syncthreads();
    }

#pragma unroll
    for (int mf = 0; mf < 4; mf++) {
        int r0 = row0 + wm + mf * 16 + (lane >> 2);
#pragma unroll
        for (int nf = 0; nf < 4; nf++) {
            int n0 = col0 + wn + nf * 8 + 2 * (lane & 3);
#pragma unroll
            for (int half = 0; half < 2; half++) {
                int r = r0 + half * 8;
#pragma unroll
                for (int j = 0; j < 2; j++) {
                    int n = n0 + j;
                    if (n < N) {
                        float v = acc[mf][nf][half * 2 + j];
                        if (EPI & 1) v += bias[n];
                        if (EPI & 2) v = fmaxf(v, 0.0f);
                        if (EPI & 4) v += resid[(size_t)r * N + n];
                        C[(size_t)r * N + n] = v;
                    }
                }
            }
        }
    }
#undef LOADT
#undef STST
}

// ---------------- smem-tiled streaming causal attention --------------------
// CTA = 32 consecutive queries of one (b,h); 8 warps x 4 queries.
// K/V staged in 32-key smem chunks shared by all warps (8x traffic cut vs
// per-warp streaming). Inner math identical to the proven streaming version.
#define SCH 32    // keys per smem chunk

__global__ __launch_bounds__(256)
void attn_kernel(const float* __restrict__ qkv, float* __restrict__ o) {
    __shared__ float Ks[SCH * NHS];   // 8 KB
    __shared__ float Vs[SCH * NHS];   // 8 KB

    const int tid  = threadIdx.x;
    const int lane = tid & 31;
    const int wi   = tid >> 5;                 // warp 0..7
    const int qblk = blockIdx.x % (NT / 32);   // 32-query block
    const int bh   = blockIdx.x / (NT / 32);
    const int b    = bh / NH, h = bh % NH;
    const int t0c  = qblk * 32;                // CTA's first query
    const int t0   = t0c + wi * 4;             // warp's first query

    const float* base = qkv + (size_t)b * NT * NQKV;
    const float* qb = base + h * NHS;
    const float* kb = base + ND + h * NHS;
    const float* vb = base + 2 * ND + h * NHS;

    float q0[4], q1[4];
#pragma unroll
    for (int i = 0; i < 4; i++) {
        q0[i] = qb[(size_t)(t0 + i) * NQKV + lane];
        q1[i] = qb[(size_t)(t0 + i) * NQKV + 32 + lane];
    }
    float m[4], l[4], a0[4], a1[4];
#pragma unroll
    for (int i = 0; i < 4; i++) { m[i] = -1e30f; l[i] = 0.f; a0[i] = 0.f; a1[i] = 0.f; }

    const float scale = 0.125f;   // HS^-0.5
    const int send = t0 + 3;      // warp's last needed key

    for (int sc = 0; sc < t0c + 32; sc += SCH) {
        // cooperative chunk load: 32 keys x 64 floats (K and V), float4
        // flat4 in [0,512): row = flat4>>4, col4 = flat4&15
#pragma unroll
        for (int j = 0; j < 2; j++) {
            int flat4 = tid * 2 + j;
            int srow = flat4 >> 4, c4 = (flat4 & 15) * 4;
            size_t goff = (size_t)(sc + srow) * NQKV + c4;
            *reinterpret_cast<float4*>(&Ks[srow * NHS + c4]) =
                *reinterpret_cast<const float4*>(kb + goff);
            *reinterpret_cast<float4*>(&Vs[srow * NHS + c4]) =
                *reinterpret_cast<const float4*>(vb + goff);
        }
        __syncthreads();

        const int L = min(SCH, send - sc + 1);   // keys this warp consumes
        for (int s = 0; s < L; s++) {
            float k0v = Ks[s * NHS + lane],      k1v = Ks[s * NHS + 32 + lane];
            float v0v = Vs[s * NHS + lane],      v1v = Vs[s * NHS + 32 + lane];
            const int sg = sc + s;
#pragma unroll
            for (int i = 0; i < 4; i++) {
                float p = q0[i] * k0v + q1[i] * k1v;
                p += __shfl_xor_sync(0xffffffffu, p, 16);
                p += __shfl_xor_sync(0xffffffffu, p, 8);
                p += __shfl_xor_sync(0xffffffffu, p, 4);
                p += __shfl_xor_sync(0xffffffffu, p, 2);
                p += __shfl_xor_sync(0xffffffffu, p, 1);
                if (sg <= t0 + i) {
                    float sc2 = p * scale;
                    float mn = fmaxf(m[i], sc2);
                    float corr = __expf(m[i] - mn);
                    float e = __expf(sc2 - mn);
                    l[i]  = l[i]  * corr + e;
                    a0[i] = a0[i] * corr + e * v0v;
                    a1[i] = a1[i] * corr + e * v1v;
                    m[i] = mn;
                }
            }
        }
        __syncthreads();
    }

#pragma unroll
    for (int i = 0; i < 4; i++) {
        size_t oo = (size_t)(b * NT + t0 + i) * ND + h * NHS + lane;
        o[oo]      = a0[i] / l[i];
        o[oo + 32] = a1[i] / l[i];
    }
}

// ---------------- loss ------------------------------------------------------
__global__ __launch_bounds__(256)
void loss_kernel(const float* __restrict__ logits, const int* __restrict__ targets) {
    __shared__ float sm_[256], sl_[256];
    int row = blockIdx.x, tid = threadIdx.x;
    const float* lr = logits + (size_t)row * NV;
    float m = -1e30f, l = 0.0f;
    for (int j = tid; j < NV; j += 256) {
        float v = lr[j];
        float mn = fmaxf(m, v);
        l = l * __expf(m - mn) + __expf(v - mn);
        m = mn;
    }
    sm_[tid] = m; sl_[tid] = l;
    __syncthreads();
    for (int off = 128; off; off >>= 1) {
        if (tid < off) {
            float m2 = sm_[tid + off], l2 = sl_[tid + off];
            float mn = fmaxf(sm_[tid], m2);
            sl_[tid] = sl_[tid] * __expf(sm_[tid] - mn) + l2 * __expf(m2 - mn);
            sm_[tid] = mn;
        }
        __syncthreads();
    }
    if (tid == 0) {
        float lp = lr[targets[row]] - sm_[0] - logf(sl_[0]);
        atomicAdd(&g_loss, -lp * (1.0f / NTOK));
    }
}

__global__ void finalize_loss_kernel(float* out, int out_size) {
    long long pos = (long long)NTOK * NV;
    if ((long long)out_size > pos) out[pos] = g_loss;
}

// ---------------- host orchestration ----------------------------------------
extern "C" void kernel_launch(void* const* d_in, const int* in_sizes, int n_in,
                              void* d_out, int out_size) {
    const int*   idx     = (const int*)d_in[0];
    const int*   targets = (const int*)d_in[1];
    const float* tok_emb = (const float*)d_in[2];
    const float* pos_emb = (const float*)d_in[3];
    const float* wq      = (const float*)d_in[4];
    const float* wk      = (const float*)d_in[5];
    const float* wv      = (const float*)d_in[6];
    const float* wo      = (const float*)d_in[7];
    const float* bo      = (const float*)d_in[8];
    const float* ln1_s   = (const float*)d_in[9];
    const float* ln1_b   = (const float*)d_in[10];
    const float* ln2_s   = (const float*)d_in[11];
    const float* ln2_b   = (const float*)d_in[12];
    const float* w1      = (const float*)d_in[13];
    const float* b1      = (const float*)d_in[14];
    const float* w2      = (const float*)d_in[15];
    const float* b2      = (const float*)d_in[16];
    const float* lnf_s   = (const float*)d_in[17];
    const float* lnf_b   = (const float*)d_in[18];
    const float* head_w  = (const float*)d_in[19];
    const float* head_b  = (const float*)d_in[20];
    float* out = (float*)d_out;
    (void)in_sizes; (void)n_in;

    float *px, *ph, *pqkv, *po, *pmlp;
    float *pwqkvT, *pwoT, *pw1T, *pw2T, *pheadT;
    cudaGetSymbolAddress((void**)&px,     g_x);
    cudaGetSymbolAddress((void**)&ph,     g_h);
    cudaGetSymbolAddress((void**)&pqkv,   g_qkv);
    cudaGetSymbolAddress((void**)&po,     g_o);
    cudaGetSymbolAddress((void**)&pmlp,   g_mlp);
    cudaGetSymbolAddress((void**)&pwqkvT, g_wqkvT);
    cudaGetSymbolAddress((void**)&pwoT,   g_woT);
    cudaGetSymbolAddress((void**)&pw1T,   g_w1T);
    cudaGetSymbolAddress((void**)&pw2T,   g_w2T);
    cudaGetSymbolAddress((void**)&pheadT, g_headT);

    reset_loss_kernel<<<1, 1>>>();
    {
        int total = NL * NQKV * ND;
        repack_qkv_kernel<<<(total + 255) / 256, 256>>>(wq, wk, wv);
    }
    {
        dim3 blk(32, 8);
        transpose_kernel<<<dim3(24, 24, NL), blk>>>(wo, pwoT, ND, ND);
        transpose_kernel<<<dim3(96, 24, NL), blk>>>(w1, pw1T, ND, NFF);
        transpose_kernel<<<dim3(24, 96, NL), blk>>>(w2, pw2T, NFF, ND);
        transpose_kernel<<<dim3((NV + 31) / 32, 24, 1), blk>>>(head_w, pheadT, ND, NV);
    }
    {
        int total = NTOK * ND;
        embed_kernel<<<(total + 255) / 256, 256>>>(idx, tok_emb, pos_emb);
    }

    // grid: x = M panels (fast) -> B column panel reused across a wave
    dim3 gQKV(NTOK / 128, NQKV / 128);
    dim3 gD(NTOK / 128, ND / 128);
    dim3 gFF(NTOK / 128, NFF / 128);
    dim3 gV(NTOK / 128, (NV + 127) / 128);

    const int attnGrid = NB * NH * (NT / 32);   // 1536 CTAs

    for (int l = 0; l < NL; l++) {
        ln_kernel<<<NTOK, 256>>>(px, ln1_s + l * ND, ln1_b + l * ND, ph);
        hgemm<0><<<gQKV, 256>>>(ph, pwqkvT + (size_t)l * NQKV * ND,
                                nullptr, nullptr, pqkv, NTOK, NQKV, ND);
        attn_kernel<<<attnGrid, 256>>>(pqkv, po);
        hgemm<5><<<gD, 256>>>(po, pwoT + (size_t)l * ND * ND,
                              bo + l * ND, px, px, NTOK, ND, ND);
        ln_kernel<<<NTOK, 256>>>(px, ln2_s + l * ND, ln2_b + l * ND, ph);
        hgemm<3><<<gFF, 256>>>(ph, pw1T + (size_t)l * ND * NFF,
                               b1 + l * NFF, nullptr, pmlp, NTOK, NFF, ND);
        hgemm<5><<<gD, 256>>>(pmlp, pw2T + (size_t)l * NFF * ND,
                              b2 + l * ND, px, px, NTOK, ND, NFF);
    }

    ln_kernel<<<NTOK, 256>>>(px, lnf_s, lnf_b, ph);
    hgemm<1><<<gV, 256>>>(ph, pheadT, head_b, nullptr, out, NTOK, NV, ND);
    loss_kernel<<<NTOK, 256>>>(out, targets);
    finalize_loss_kernel<<<1, 1>>>(out, out_size);
}